// round 11
// baseline (speedup 1.0000x reference)
#include <cuda_runtime.h>
#include <math.h>

#define BSZ 256
#define CC  256
#define II  256
#define JJ  32
#define DD  64
#define TI  64
#define NQ  4

#define XS  68   // xt row stride (16B-aligned rows for LDS.128, conflict-free)
#define CSA 68   // ctA/ctB row stride
#define US  257  // usm row stride (scalar broadcast reads)
#define WS  258
#define YS  258
#define SS  65

typedef unsigned long long ull;

__device__ __forceinline__ ull ffma2(ull a, ull b, ull c) {
    ull d; asm("fma.rn.f32x2 %0, %1, %2, %3;" : "=l"(d) : "l"(a), "l"(b), "l"(c));
    return d;
}
__device__ __forceinline__ ull fadd2(ull a, ull b) {
    ull d; asm("add.rn.f32x2 %0, %1, %2;" : "=l"(d) : "l"(a), "l"(b));
    return d;
}
__device__ __forceinline__ ull fpack2(float x) {
    ull d; unsigned r = __float_as_uint(x);
    asm("mov.b64 %0, {%1, %1};" : "=l"(d) : "r"(r));
    return d;
}
__device__ __forceinline__ float f2sum(ull v) {
    unsigned lo, hi;
    asm("mov.b64 {%0, %1}, %2;" : "=r"(lo), "=r"(hi) : "l"(v));
    return __uint_as_float(lo) + __uint_as_float(hi);
}
__device__ __forceinline__ ull lds2(const float* p) {
    return *reinterpret_cast<const ull*>(p);
}
__device__ __forceinline__ void sts2(float* p, ull v) {
    *reinterpret_cast<ull*>(p) = v;
}

// Scratch (no runtime allocation allowed)
__device__ float g_y[BSZ * NQ * JJ * CC];
__device__ float g_u[BSZ * JJ * CC];
__device__ float g_blog[BSZ * JJ * II];
__device__ float g_csum[BSZ * NQ * JJ];
__device__ float g_vb[BSZ * JJ];

// ---------------------------------------------------------------------------
// capsA: one CTA per (batch, i-quarter of 64 columns).
// ---------------------------------------------------------------------------
__global__ __launch_bounds__(256, 2)
void capsA(const float* __restrict__ x, const float* __restrict__ b_prev_in,
           int first, int write_b)
{
    extern __shared__ float sm[];
    float* xt  = sm;                    // [256][XS]
    float* usm = xt + 256 * XS;         // [32][US]; ctB aliases this region
    float* ctB = usm;                   // [32][CSA] (valid only after usm dead)
    float* ctA = usm + 32 * US;         // [32][CSA]
    float* vbs = ctA + 32 * CSA;        // [32]

    const int b  = blockIdx.x >> 2;
    const int q  = blockIdx.x & 3;
    const int i0 = q * TI;
    const int t  = threadIdx.x;
    const float* xb = x + (size_t)b * (CC * II);
    const float* bp_base = b_prev_in ? b_prev_in : g_blog;

    if (!first) {
        const float4* ub4 = reinterpret_cast<const float4*>(g_u + (size_t)b * (JJ * CC));
#pragma unroll
        for (int it = 0; it < 8; it++) {
            int i4  = t + it * 256;
            int row = i4 >> 6;
            int c4  = (i4 & 63) * 4;
            float4 v = ub4[i4];
            float* dst = &usm[row * US + c4];
            dst[0] = v.x; dst[1] = v.y; dst[2] = v.z; dst[3] = v.w;
        }
        if (t < JJ) vbs[t] = g_vb[b * JJ + t];
    }

    // stage x[:, i0:i0+64] -> xt[c][i-i0]  (float4 in/out; 16B-aligned)
    {
        const int qq   = t & 3;
        const int row0 = t >> 2;
#pragma unroll
        for (int rep = 0; rep < 4; rep++) {
            const int c = row0 + rep * 64;
            const float4* src =
                reinterpret_cast<const float4*>(xb + (size_t)c * II + i0 + qq * 16);
            float4* dst = reinterpret_cast<float4*>(&xt[c * XS + qq * 16]);
#pragma unroll
            for (int k = 0; k < 4; k++) dst[k] = src[k];
        }
    }
    __syncthreads();

    if (!first) {
        // delta GEMM: out [32 j][64 i] packed as i-pairs; split-K4 over c.
        const int h   = t >> 6;      // 0..3, c-quarter
        const int p   = t & 63;
        const int ipb = p & 7;       // ipair = ipb + 8*r
        const int jb  = p >> 3;      // j = jb*4 + n
        ull acc2[4][4];
#pragma unroll
        for (int n = 0; n < 4; n++)
#pragma unroll
            for (int r = 0; r < 4; r++) acc2[n][r] = 0ull;
        const int c0 = h * 64;
#pragma unroll 4
        for (int c = c0; c < c0 + 64; c++) {
            ull uv2[4], xv2[4];
#pragma unroll
            for (int n = 0; n < 4; n++) uv2[n] = fpack2(usm[(jb * 4 + n) * US + c]);
#pragma unroll
            for (int r = 0; r < 4; r++) xv2[r] = lds2(&xt[c * XS + 2 * (ipb + 8 * r)]);
#pragma unroll
            for (int n = 0; n < 4; n++)
#pragma unroll
                for (int r = 0; r < 4; r++)
                    acc2[n][r] = ffma2(uv2[n], xv2[r], acc2[n][r]);
        }
        __syncthreads();   // all usm reads done; ctB region now reusable
        if (h == 0) {
#pragma unroll
            for (int n = 0; n < 4; n++)
#pragma unroll
                for (int r = 0; r < 4; r++)
                    sts2(&ctA[(jb * 4 + n) * CSA + 2 * (ipb + 8 * r)], acc2[n][r]);
        }
        if (h == 1) {
#pragma unroll
            for (int n = 0; n < 4; n++)
#pragma unroll
                for (int r = 0; r < 4; r++)
                    sts2(&ctB[(jb * 4 + n) * CSA + 2 * (ipb + 8 * r)], acc2[n][r]);
        }
        __syncthreads();
        if (h == 2) {
#pragma unroll
            for (int n = 0; n < 4; n++)
#pragma unroll
                for (int r = 0; r < 4; r++) {
                    float* pp = &ctA[(jb * 4 + n) * CSA + 2 * (ipb + 8 * r)];
                    sts2(pp, fadd2(lds2(pp), acc2[n][r]));
                }
        }
        if (h == 3) {
#pragma unroll
            for (int n = 0; n < 4; n++)
#pragma unroll
                for (int r = 0; r < 4; r++) {
                    float* pp = &ctB[(jb * 4 + n) * CSA + 2 * (ipb + 8 * r)];
                    sts2(pp, fadd2(lds2(pp), acc2[n][r]));
                }
        }
        __syncthreads();
    }

    // softmax over j per column i (64 columns, one thread each)
    if (t < TI) {
        const int i = i0 + t;
        const float* bp = bp_base + (size_t)b * (JJ * II) + i;
        float bv[32];
        float mx = -3.4e38f;
#pragma unroll
        for (int j = 0; j < 32; j++) {
            float val = bp[j * II];
            if (!first) val += ctA[j * CSA + t] + ctB[j * CSA + t] + vbs[j];
            bv[j] = val;
            mx = fmaxf(mx, val);
        }
        if (write_b) {
            float* bo = g_blog + (size_t)b * (JJ * II) + i;
#pragma unroll
            for (int j = 0; j < 32; j++) bo[j * II] = bv[j];
        }
        float Z = 0.f;
#pragma unroll
        for (int j = 0; j < 32; j++) { float e = expf(bv[j] - mx); bv[j] = e; Z += e; }
        const float inv = 1.f / Z;
#pragma unroll
        for (int j = 0; j < 32; j++) ctA[j * CSA + t] = bv[j] * inv;
    }
    __syncthreads();

    // csum partial
    if (t < 32) {
        float s = 0.f;
#pragma unroll 8
        for (int i = 0; i < TI; i++) s += ctA[t * CSA + i];
        g_csum[(b * 4 + q) * JJ + t] = s;
    }

    // y GEMM partial: 8j x 4c tile per thread, i-pairs packed; LDS.128 loads
    const int lane = t & 31;
    const int w    = t >> 5;
    const int g    = w >> 1;     // j-group: j = g*8 + n
    const int hc   = w & 1;      // c-half: c = hc*128 + lane + 32*m
    ull acc[8][4];
#pragma unroll
    for (int n = 0; n < 8; n++)
#pragma unroll
        for (int m = 0; m < 4; m++) acc[n][m] = 0ull;

#pragma unroll 2
    for (int ip2 = 0; ip2 < TI / 4; ip2++) {
        ulonglong2 xv[4];
#pragma unroll
        for (int m = 0; m < 4; m++)
            xv[m] = *reinterpret_cast<const ulonglong2*>(
                &xt[(hc * 128 + lane + 32 * m) * XS + 4 * ip2]);
#pragma unroll
        for (int n = 0; n < 8; n++) {
            ulonglong2 cf = *reinterpret_cast<const ulonglong2*>(
                &ctA[(g * 8 + n) * CSA + 4 * ip2]);
#pragma unroll
            for (int m = 0; m < 4; m++) {
                acc[n][m] = ffma2(cf.x, xv[m].x, acc[n][m]);
                acc[n][m] = ffma2(cf.y, xv[m].y, acc[n][m]);
            }
        }
    }

    float* yb = g_y + (size_t)(b * 4 + q) * (JJ * CC);
#pragma unroll
    for (int n = 0; n < 8; n++)
#pragma unroll
        for (int m = 0; m < 4; m++)
            yb[(g * 8 + n) * CC + hc * 128 + lane + 32 * m] = f2sum(acc[n][m]);
}

// ---------------------------------------------------------------------------
// capsB: one CTA per (j, batch-group of 32).
// ---------------------------------------------------------------------------
__global__ __launch_bounds__(256, 2)
void capsB(const float* __restrict__ W, const float* __restrict__ bias,
           float* __restrict__ out, int last)
{
    extern __shared__ float sm[];
    float* Wsm = sm;               // [64][WS]
    float* ysm = Wsm + 64 * WS;    // [32][YS]
    float* ssm = ysm + 32 * YS;    // [32][SS]
    float* bsm = ssm + 32 * SS;    // [64]
    float* fsm = bsm + 64;         // [32]
    float* csv = fsm + 32;         // [32]

    const int j  = blockIdx.x & 31;
    const int bg = blockIdx.x >> 5;
    const int t  = threadIdx.x;

    // stage W_j
    {
        const float4* Wj4 = reinterpret_cast<const float4*>(W + (size_t)j * (DD * CC));
#pragma unroll
        for (int it = 0; it < 16; it++) {
            int i4  = t + it * 256;
            int row = i4 >> 6;
            int c   = (i4 & 63) * 4;
            float4 v = Wj4[i4];
            float* dst = &Wsm[row * WS + c];
            dst[0] = v.x; dst[1] = v.y; dst[2] = v.z; dst[3] = v.w;
        }
    }
    if (t < DD) bsm[t] = bias[j * DD + t];
    if (t < 32) {
        float cs = 0.f;
#pragma unroll
        for (int q = 0; q < 4; q++)
            cs += g_csum[((bg * 32 + t) * 4 + q) * JJ + j];
        csv[t] = cs;
    }
    // stage y = sum of 4 quarter partials
    {
#pragma unroll
        for (int it = 0; it < 8; it++) {
            int i4 = t + it * 256;
            int bb = i4 >> 6;
            int c4 = i4 & 63;
            float4 a = make_float4(0.f, 0.f, 0.f, 0.f);
#pragma unroll
            for (int q = 0; q < 4; q++) {
                const float4* src = reinterpret_cast<const float4*>(
                    g_y + ((size_t)((bg * 32 + bb) * 4 + q) * JJ + j) * CC);
                float4 v = src[c4];
                a.x += v.x; a.y += v.y; a.z += v.z; a.w += v.w;
            }
            float* dst = &ysm[bb * YS + c4 * 4];
            dst[0] = a.x; dst[1] = a.y; dst[2] = a.z; dst[3] = a.w;
        }
    }
    __syncthreads();

    // GEMM1: S[32 b][64 d], K-packed over c, split-K2
    {
        const int h   = t >> 7;
        const int p   = t & 127;
        const int db  = p & 15;
        const int bgr = p >> 4;
        ull acc2[4][4];
#pragma unroll
        for (int n = 0; n < 4; n++)
#pragma unroll
            for (int r = 0; r < 4; r++) acc2[n][r] = 0ull;
        const int cp0 = h * 64;
#pragma unroll 4
        for (int cp = cp0; cp < cp0 + 64; cp++) {
            ull yv2[4], wv2[4];
#pragma unroll
            for (int n = 0; n < 4; n++) yv2[n] = lds2(&ysm[(bgr * 4 + n) * YS + 2 * cp]);
#pragma unroll
            for (int r = 0; r < 4; r++) wv2[r] = lds2(&Wsm[(db + 16 * r) * WS + 2 * cp]);
#pragma unroll
            for (int n = 0; n < 4; n++)
#pragma unroll
                for (int r = 0; r < 4; r++)
                    acc2[n][r] = ffma2(yv2[n], wv2[r], acc2[n][r]);
        }
        if (h == 0) {
#pragma unroll
            for (int n = 0; n < 4; n++)
#pragma unroll
                for (int r = 0; r < 4; r++)
                    ssm[(bgr * 4 + n) * SS + db + 16 * r] = f2sum(acc2[n][r]);
        }
        __syncthreads();
        if (h == 1) {
#pragma unroll
            for (int n = 0; n < 4; n++)
#pragma unroll
                for (int r = 0; r < 4; r++)
                    ssm[(bgr * 4 + n) * SS + db + 16 * r] += f2sum(acc2[n][r]);
        }
        __syncthreads();
    }

    // + csum*bias
#pragma unroll
    for (int k = 0; k < 8; k++) {
        int idx = t + k * 256;
        int bb = idx >> 6, d = idx & 63;
        ssm[bb * SS + d] += csv[bb] * bsm[d];
    }
    __syncthreads();

    // squash factor per batch: 8 lanes per b, butterfly reduce
    {
        const int bb = t >> 3, dg = t & 7;
        float p2 = 0.f;
#pragma unroll
        for (int k = 0; k < 8; k++) {
            float s = ssm[bb * SS + dg + 8 * k];
            p2 = fmaf(s, s, p2);
        }
        p2 += __shfl_xor_sync(0xffffffffu, p2, 4);
        p2 += __shfl_xor_sync(0xffffffffu, p2, 2);
        p2 += __shfl_xor_sync(0xffffffffu, p2, 1);
        if (dg == 0) {
            const float nn = sqrtf(p2);
            fsm[bb] = nn / (1.f + p2);
        }
    }
    __syncthreads();

    // v = s*factor in place; write output if last
#pragma unroll
    for (int k = 0; k < 8; k++) {
        int idx = t + k * 256;
        int bb = idx >> 6, d = idx & 63;
        float v = ssm[bb * SS + d] * fsm[bb];
        ssm[bb * SS + d] = v;
        if (last) out[((size_t)(bg * 32 + bb) * JJ + j) * DD + d] = v;
    }
    __syncthreads();

    if (!last) {
        // vb[b] = v . bias  (8 lanes per b)
        {
            const int bb = t >> 3, dg = t & 7;
            float p3 = 0.f;
#pragma unroll
            for (int k = 0; k < 8; k++)
                p3 = fmaf(ssm[bb * SS + dg + 8 * k], bsm[dg + 8 * k], p3);
            p3 += __shfl_xor_sync(0xffffffffu, p3, 4);
            p3 += __shfl_xor_sync(0xffffffffu, p3, 2);
            p3 += __shfl_xor_sync(0xffffffffu, p3, 1);
            if (dg == 0) g_vb[(bg * 32 + bb) * JJ + j] = p3;
        }
        // GEMM2: U[32 b][256 c] output-packed along c, K = 64
        const int ci = t & 31;
        const int bi = t >> 5;
        ull ua2[4][4];
#pragma unroll
        for (int n = 0; n < 4; n++)
#pragma unroll
            for (int m = 0; m < 4; m++) ua2[n][m] = 0ull;
#pragma unroll 4
        for (int d = 0; d < 64; d++) {
            ull vv2[4], wv2[4];
#pragma unroll
            for (int n = 0; n < 4; n++) vv2[n] = fpack2(ssm[(bi + 8 * n) * SS + d]);
#pragma unroll
            for (int m = 0; m < 4; m++) wv2[m] = lds2(&Wsm[d * WS + 2 * (ci + 32 * m)]);
#pragma unroll
            for (int n = 0; n < 4; n++)
#pragma unroll
                for (int m = 0; m < 4; m++)
                    ua2[n][m] = ffma2(vv2[n], wv2[m], ua2[n][m]);
        }
#pragma unroll
        for (int n = 0; n < 4; n++)
#pragma unroll
            for (int m = 0; m < 4; m++)
                *reinterpret_cast<ull*>(
                    &g_u[((size_t)(bg * 32 + bi + 8 * n) * JJ + j) * CC
                         + 2 * (ci + 32 * m)]) = ua2[n][m];
    }
}

extern "C" void kernel_launch(void* const* d_in, const int* in_sizes, int n_in,
                              void* d_out, int out_size)
{
    const float* x     = (const float*)d_in[0];
    const float* W     = (const float*)d_in[1];
    const float* bias  = (const float*)d_in[2];
    const float* binit = (const float*)d_in[3];
    float* out = (float*)d_out;

    const int SMEM_A = (256 * XS + 32 * US + 32 * CSA + 32) * (int)sizeof(float);
    const int SMEM_B = (64 * WS + 32 * YS + 32 * SS + 64 + 32 + 32) * (int)sizeof(float);

    cudaFuncSetAttribute(capsA, cudaFuncAttributeMaxDynamicSharedMemorySize, SMEM_A);
    cudaFuncSetAttribute(capsB, cudaFuncAttributeMaxDynamicSharedMemorySize, SMEM_B);

    capsA<<<BSZ * NQ, 256, SMEM_A>>>(x, binit, /*first=*/1, /*write_b=*/0);
    capsB<<<256, 256, SMEM_B>>>(W, bias, nullptr, /*last=*/0);
    capsA<<<BSZ * NQ, 256, SMEM_A>>>(x, binit, 0, 1);
    capsB<<<256, 256, SMEM_B>>>(W, bias, nullptr, 0);
    capsA<<<BSZ * NQ, 256, SMEM_A>>>(x, nullptr, 0, 0);
    capsB<<<256, 256, SMEM_B>>>(W, bias, out, 1);
}

// round 12
// speedup vs baseline: 1.5004x; 1.5004x over previous
#include <cuda_runtime.h>
#include <math.h>

#define BSZ 256
#define CC  256
#define II  256
#define JJ  32
#define DD  64
#define TI  64
#define NQ  4

#define XS 66    // xt row stride (even -> 8B-aligned pair loads)
#define US 257   // usm row stride (scalar reads only)
#define CS 66    // ct row stride
#define WS 258   // Wsm row stride
#define YS 258   // ysm row stride
#define SS 65    // ssm row stride (scalar reads only)

typedef unsigned long long ull;

__device__ __forceinline__ ull ffma2(ull a, ull b, ull c) {
    ull d; asm("fma.rn.f32x2 %0, %1, %2, %3;" : "=l"(d) : "l"(a), "l"(b), "l"(c));
    return d;
}
__device__ __forceinline__ ull fadd2(ull a, ull b) {
    ull d; asm("add.rn.f32x2 %0, %1, %2;" : "=l"(d) : "l"(a), "l"(b));
    return d;
}
__device__ __forceinline__ ull fpack2(float x) {
    ull d; unsigned r = __float_as_uint(x);
    asm("mov.b64 %0, {%1, %1};" : "=l"(d) : "r"(r));
    return d;
}
__device__ __forceinline__ float f2sum(ull v) {
    unsigned lo, hi;
    asm("mov.b64 {%0, %1}, %2;" : "=r"(lo), "=r"(hi) : "l"(v));
    return __uint_as_float(lo) + __uint_as_float(hi);
}
__device__ __forceinline__ ull lds2(const float* p) {
    return *reinterpret_cast<const ull*>(p);
}
__device__ __forceinline__ void sts2(float* p, ull v) {
    *reinterpret_cast<ull*>(p) = v;
}

// Scratch (no runtime allocation allowed)
__device__ float g_y[BSZ * NQ * JJ * CC];
__device__ float g_u[BSZ * JJ * CC];
__device__ float g_blog[BSZ * JJ * II];
__device__ float g_csum[BSZ * NQ * JJ];
__device__ float g_vb[BSZ * JJ];

// ---------------------------------------------------------------------------
// capsA: one CTA per (batch, i-quarter of 64 columns).
// ---------------------------------------------------------------------------
__global__ __launch_bounds__(256, 2)
void capsA(const float* __restrict__ x, const float* __restrict__ b_prev_in,
           int first, int write_b)
{
    extern __shared__ float sm[];
    float* xt  = sm;                    // [256][XS]
    float* usm = xt + 256 * XS;         // [32][US]
    float* ct  = usm + 32 * US;         // [32][CS]
    float* vbs = ct + 32 * CS;          // [32]

    const int b  = blockIdx.x >> 2;
    const int q  = blockIdx.x & 3;
    const int i0 = q * TI;
    const int t  = threadIdx.x;
    const float* xb = x + (size_t)b * (CC * II);
    const float* bp_base = b_prev_in ? b_prev_in : g_blog;

    if (!first) {
        const float4* ub4 = reinterpret_cast<const float4*>(g_u + (size_t)b * (JJ * CC));
#pragma unroll
        for (int it = 0; it < 8; it++) {
            int i4  = t + it * 256;          // 0..2047
            int row = i4 >> 6;
            int c4  = (i4 & 63) * 4;
            float4 v = ub4[i4];
            float* dst = &usm[row * US + c4];
            dst[0] = v.x; dst[1] = v.y; dst[2] = v.z; dst[3] = v.w;
        }
        if (t < JJ) vbs[t] = g_vb[b * JJ + t];
    }

    // stage x[:, i0:i0+64] -> xt[c][i-i0]
    {
        const int qq   = t & 3;
        const int row0 = t >> 2;
#pragma unroll
        for (int rep = 0; rep < 4; rep++) {
            const int c = row0 + rep * 64;
            const float4* src =
                reinterpret_cast<const float4*>(xb + (size_t)c * II + i0 + qq * 16);
            float* dst = &xt[c * XS + qq * 16];
#pragma unroll
            for (int k = 0; k < 4; k++) {
                float4 v4 = src[k];
                dst[k * 4 + 0] = v4.x; dst[k * 4 + 1] = v4.y;
                dst[k * 4 + 2] = v4.z; dst[k * 4 + 3] = v4.w;
            }
        }
    }
    __syncthreads();

    if (!first) {
        // delta GEMM: out [32 j][64 i] packed as i-pairs; split-K4 over c.
        const int h   = t >> 6;      // 0..3, c-quarter
        const int p   = t & 63;
        const int ipb = p & 7;       // ipair = ipb + 8*r
        const int jb  = p >> 3;      // j = jb*4 + n
        ull acc2[4][4];
#pragma unroll
        for (int n = 0; n < 4; n++)
#pragma unroll
            for (int r = 0; r < 4; r++) acc2[n][r] = 0ull;
        const int c0 = h * 64;
#pragma unroll 4
        for (int c = c0; c < c0 + 64; c++) {
            ull uv2[4], xv2[4];
#pragma unroll
            for (int n = 0; n < 4; n++) uv2[n] = fpack2(usm[(jb * 4 + n) * US + c]);
#pragma unroll
            for (int r = 0; r < 4; r++) xv2[r] = lds2(&xt[c * XS + 2 * (ipb + 8 * r)]);
#pragma unroll
            for (int n = 0; n < 4; n++)
#pragma unroll
                for (int r = 0; r < 4; r++)
                    acc2[n][r] = ffma2(uv2[n], xv2[r], acc2[n][r]);
        }
        // serialized split-K reduction into ct
        if (h == 0) {
#pragma unroll
            for (int n = 0; n < 4; n++)
#pragma unroll
                for (int r = 0; r < 4; r++)
                    sts2(&ct[(jb * 4 + n) * CS + 2 * (ipb + 8 * r)], acc2[n][r]);
        }
        __syncthreads();
#pragma unroll
        for (int hh = 1; hh < 4; hh++) {
            if (h == hh) {
#pragma unroll
                for (int n = 0; n < 4; n++)
#pragma unroll
                    for (int r = 0; r < 4; r++) {
                        float* pp = &ct[(jb * 4 + n) * CS + 2 * (ipb + 8 * r)];
                        sts2(pp, fadd2(lds2(pp), acc2[n][r]));
                    }
            }
            __syncthreads();
        }
    }

    // softmax over j per column i (64 columns, one thread each)
    if (t < TI) {
        const int i = i0 + t;
        const float* bp = bp_base + (size_t)b * (JJ * II) + i;
        float bv[32];
        float mx = -3.4e38f;
#pragma unroll
        for (int j = 0; j < 32; j++) {
            float val = bp[j * II];
            if (!first) val += ct[j * CS + t] + vbs[j];
            bv[j] = val;
            mx = fmaxf(mx, val);
        }
        if (write_b) {
            float* bo = g_blog + (size_t)b * (JJ * II) + i;
#pragma unroll
            for (int j = 0; j < 32; j++) bo[j * II] = bv[j];
        }
        float Z = 0.f;
#pragma unroll
        for (int j = 0; j < 32; j++) { float e = expf(bv[j] - mx); bv[j] = e; Z += e; }
        const float inv = 1.f / Z;
#pragma unroll
        for (int j = 0; j < 32; j++) ct[j * CS + t] = bv[j] * inv;
    }
    __syncthreads();

    // csum partial
    if (t < 32) {
        float s = 0.f;
#pragma unroll 8
        for (int i = 0; i < TI; i++) s += ct[t * CS + i];
        g_csum[(b * 4 + q) * JJ + t] = s;
    }

    // y GEMM partial (K-packed along i): y[j,c] = sum_i c[j,i]*x[c,i]
    const int lane_c = t & 31;
    const int jby    = t >> 5;
    ull yacc2[4][8];
#pragma unroll
    for (int n = 0; n < 4; n++)
#pragma unroll
        for (int m = 0; m < 8; m++) yacc2[n][m] = 0ull;

#pragma unroll 2
    for (int ip = 0; ip < TI / 2; ip++) {
        ull cf2[4], xv2[8];
#pragma unroll
        for (int n = 0; n < 4; n++) cf2[n] = lds2(&ct[(jby * 4 + n) * CS + 2 * ip]);
#pragma unroll
        for (int m = 0; m < 8; m++) xv2[m] = lds2(&xt[(lane_c + 32 * m) * XS + 2 * ip]);
#pragma unroll
        for (int m = 0; m < 8; m++)
#pragma unroll
            for (int n = 0; n < 4; n++)
                yacc2[n][m] = ffma2(cf2[n], xv2[m], yacc2[n][m]);
    }

    float* yb = g_y + (size_t)(b * 4 + q) * (JJ * CC);
#pragma unroll
    for (int n = 0; n < 4; n++)
#pragma unroll
        for (int m = 0; m < 8; m++)
            yb[(jby * 4 + n) * CC + lane_c + 32 * m] = f2sum(yacc2[n][m]);
}

// ---------------------------------------------------------------------------
// capsB: one CTA per (j, batch-group of 32).
// ---------------------------------------------------------------------------
__global__ __launch_bounds__(256, 2)
void capsB(const float* __restrict__ W, const float* __restrict__ bias,
           float* __restrict__ out, int last)
{
    extern __shared__ float sm[];
    float* Wsm = sm;               // [64][WS]
    float* ysm = Wsm + 64 * WS;    // [32][YS]
    float* ssm = ysm + 32 * YS;    // [32][SS]
    float* bsm = ssm + 32 * SS;    // [64]
    float* fsm = bsm + 64;         // [32]
    float* csv = fsm + 32;         // [32]

    const int j  = blockIdx.x & 31;
    const int bg = blockIdx.x >> 5;
    const int t  = threadIdx.x;

    // stage W_j
    {
        const float4* Wj4 = reinterpret_cast<const float4*>(W + (size_t)j * (DD * CC));
#pragma unroll
        for (int it = 0; it < 16; it++) {
            int i4  = t + it * 256;
            int row = i4 >> 6;
            int c   = (i4 & 63) * 4;
            float4 v = Wj4[i4];
            float* dst = &Wsm[row * WS + c];
            dst[0] = v.x; dst[1] = v.y; dst[2] = v.z; dst[3] = v.w;
        }
    }
    if (t < DD) bsm[t] = bias[j * DD + t];
    if (t < 32) {
        float cs = 0.f;
#pragma unroll
        for (int q = 0; q < 4; q++)
            cs += g_csum[((bg * 32 + t) * 4 + q) * JJ + j];
        csv[t] = cs;
    }
    // stage y = sum of 4 quarter partials
    {
#pragma unroll
        for (int it = 0; it < 8; it++) {
            int i4 = t + it * 256;
            int bb = i4 >> 6;
            int c4 = i4 & 63;
            float4 a = make_float4(0.f, 0.f, 0.f, 0.f);
#pragma unroll
            for (int q = 0; q < 4; q++) {
                const float4* src = reinterpret_cast<const float4*>(
                    g_y + ((size_t)((bg * 32 + bb) * 4 + q) * JJ + j) * CC);
                float4 v = src[c4];
                a.x += v.x; a.y += v.y; a.z += v.z; a.w += v.w;
            }
            float* dst = &ysm[bb * YS + c4 * 4];
            dst[0] = a.x; dst[1] = a.y; dst[2] = a.z; dst[3] = a.w;
        }
    }
    __syncthreads();

    // GEMM1: S[32 b][64 d], K-packed over c, split-K2
    {
        const int h   = t >> 7;
        const int p   = t & 127;
        const int db  = p & 15;
        const int bgr = p >> 4;
        ull acc2[4][4];
#pragma unroll
        for (int n = 0; n < 4; n++)
#pragma unroll
            for (int r = 0; r < 4; r++) acc2[n][r] = 0ull;
        const int cp0 = h * 64;
#pragma unroll 4
        for (int cp = cp0; cp < cp0 + 64; cp++) {
            ull yv2[4], wv2[4];
#pragma unroll
            for (int n = 0; n < 4; n++) yv2[n] = lds2(&ysm[(bgr * 4 + n) * YS + 2 * cp]);
#pragma unroll
            for (int r = 0; r < 4; r++) wv2[r] = lds2(&Wsm[(db + 16 * r) * WS + 2 * cp]);
#pragma unroll
            for (int n = 0; n < 4; n++)
#pragma unroll
                for (int r = 0; r < 4; r++)
                    acc2[n][r] = ffma2(yv2[n], wv2[r], acc2[n][r]);
        }
        if (h == 0) {
#pragma unroll
            for (int n = 0; n < 4; n++)
#pragma unroll
                for (int r = 0; r < 4; r++)
                    ssm[(bgr * 4 + n) * SS + db + 16 * r] = f2sum(acc2[n][r]);
        }
        __syncthreads();
        if (h == 1) {
#pragma unroll
            for (int n = 0; n < 4; n++)
#pragma unroll
                for (int r = 0; r < 4; r++)
                    ssm[(bgr * 4 + n) * SS + db + 16 * r] += f2sum(acc2[n][r]);
        }
        __syncthreads();
    }

    // + csum*bias
#pragma unroll
    for (int k = 0; k < 8; k++) {
        int idx = t + k * 256;
        int bb = idx >> 6, d = idx & 63;
        ssm[bb * SS + d] += csv[bb] * bsm[d];
    }
    __syncthreads();

    // squash factor per batch: 8 lanes per b, butterfly reduce
    {
        const int bb = t >> 3, dg = t & 7;
        float p2 = 0.f;
#pragma unroll
        for (int k = 0; k < 8; k++) {
            float s = ssm[bb * SS + dg + 8 * k];
            p2 = fmaf(s, s, p2);
        }
        p2 += __shfl_xor_sync(0xffffffffu, p2, 4);
        p2 += __shfl_xor_sync(0xffffffffu, p2, 2);
        p2 += __shfl_xor_sync(0xffffffffu, p2, 1);
        if (dg == 0) {
            const float nn = sqrtf(p2);
            fsm[bb] = nn / (1.f + p2);
        }
    }
    __syncthreads();

    // v = s*factor in place; write output if last
#pragma unroll
    for (int k = 0; k < 8; k++) {
        int idx = t + k * 256;
        int bb = idx >> 6, d = idx & 63;
        float v = ssm[bb * SS + d] * fsm[bb];
        ssm[bb * SS + d] = v;
        if (last) out[((size_t)(bg * 32 + bb) * JJ + j) * DD + d] = v;
    }
    __syncthreads();

    if (!last) {
        // vb[b] = v . bias  (8 lanes per b, butterfly reduce)
        {
            const int bb = t >> 3, dg = t & 7;
            float p3 = 0.f;
#pragma unroll
            for (int k = 0; k < 8; k++)
                p3 = fmaf(ssm[bb * SS + dg + 8 * k], bsm[dg + 8 * k], p3);
            p3 += __shfl_xor_sync(0xffffffffu, p3, 4);
            p3 += __shfl_xor_sync(0xffffffffu, p3, 2);
            p3 += __shfl_xor_sync(0xffffffffu, p3, 1);
            if (dg == 0) g_vb[(bg * 32 + bb) * JJ + j] = p3;
        }
        // GEMM2: U[32 b][256 c] output-packed along c, K = 64
        const int ci = t & 31;   // cpair = ci + 32*m
        const int bi = t >> 5;   // b = bi + 8*n
        ull ua2[4][4];
#pragma unroll
        for (int n = 0; n < 4; n++)
#pragma unroll
            for (int m = 0; m < 4; m++) ua2[n][m] = 0ull;
#pragma unroll 4
        for (int d = 0; d < 64; d++) {
            ull vv2[4], wv2[4];
#pragma unroll
            for (int n = 0; n < 4; n++) vv2[n] = fpack2(ssm[(bi + 8 * n) * SS + d]);
#pragma unroll
            for (int m = 0; m < 4; m++) wv2[m] = lds2(&Wsm[d * WS + 2 * (ci + 32 * m)]);
#pragma unroll
            for (int n = 0; n < 4; n++)
#pragma unroll
                for (int m = 0; m < 4; m++)
                    ua2[n][m] = ffma2(vv2[n], wv2[m], ua2[n][m]);
        }
#pragma unroll
        for (int n = 0; n < 4; n++)
#pragma unroll
            for (int m = 0; m < 4; m++)
                *reinterpret_cast<ull*>(
                    &g_u[((size_t)(bg * 32 + bi + 8 * n) * JJ + j) * CC
                         + 2 * (ci + 32 * m)]) = ua2[n][m];
    }
}

extern "C" void kernel_launch(void* const* d_in, const int* in_sizes, int n_in,
                              void* d_out, int out_size)
{
    const float* x     = (const float*)d_in[0];
    const float* W     = (const float*)d_in[1];
    const float* bias  = (const float*)d_in[2];
    const float* binit = (const float*)d_in[3];
    float* out = (float*)d_out;

    const int SMEM_A = (256 * XS + 32 * US + 32 * CS + 32) * (int)sizeof(float);
    const int SMEM_B = (64 * WS + 32 * YS + 32 * SS + 64 + 32 + 32) * (int)sizeof(float);

    cudaFuncSetAttribute(capsA, cudaFuncAttributeMaxDynamicSharedMemorySize, SMEM_A);
    cudaFuncSetAttribute(capsB, cudaFuncAttributeMaxDynamicSharedMemorySize, SMEM_B);

    capsA<<<BSZ * NQ, 256, SMEM_A>>>(x, binit, /*first=*/1, /*write_b=*/0);
    capsB<<<256, 256, SMEM_B>>>(W, bias, nullptr, /*last=*/0);
    capsA<<<BSZ * NQ, 256, SMEM_A>>>(x, binit, 0, 1);
    capsB<<<256, 256, SMEM_B>>>(W, bias, nullptr, 0);
    capsA<<<BSZ * NQ, 256, SMEM_A>>>(x, nullptr, 0, 0);
    capsB<<<256, 256, SMEM_B>>>(W, bias, out, 1);
}

// round 15
// speedup vs baseline: 1.5139x; 1.0090x over previous
#include <cuda_runtime.h>
#include <math.h>

#define BSZ 256
#define CC  256
#define II  256
#define JJ  32
#define DD  64
#define TI  64
#define NQ  4

#define XS 66    // xt row stride (even -> 8B-aligned pair loads)
#define US 257   // usm row stride (scalar reads only)
#define CS 66    // ct row stride
#define WS 258   // Wsm row stride
#define YS 258   // ysm row stride
#define SS 65    // ssm row stride (scalar reads only)

typedef unsigned long long ull;

__device__ __forceinline__ ull ffma2(ull a, ull b, ull c) {
    ull d; asm("fma.rn.f32x2 %0, %1, %2, %3;" : "=l"(d) : "l"(a), "l"(b), "l"(c));
    return d;
}
__device__ __forceinline__ ull fadd2(ull a, ull b) {
    ull d; asm("add.rn.f32x2 %0, %1, %2;" : "=l"(d) : "l"(a), "l"(b));
    return d;
}
__device__ __forceinline__ ull fpack2(float x) {
    ull d; unsigned r = __float_as_uint(x);
    asm("mov.b64 %0, {%1, %1};" : "=l"(d) : "r"(r));
    return d;
}
__device__ __forceinline__ float f2sum(ull v) {
    unsigned lo, hi;
    asm("mov.b64 {%0, %1}, %2;" : "=r"(lo), "=r"(hi) : "l"(v));
    return __uint_as_float(lo) + __uint_as_float(hi);
}
__device__ __forceinline__ ull lds2(const float* p) {
    return *reinterpret_cast<const ull*>(p);
}
__device__ __forceinline__ void sts2(float* p, ull v) {
    *reinterpret_cast<ull*>(p) = v;
}

// Scratch (no runtime allocation allowed)
__device__ float g_y[BSZ * NQ * JJ * CC];
__device__ float g_u[BSZ * JJ * CC];
__device__ float g_blog[BSZ * JJ * II];
__device__ float g_csum[BSZ * NQ * JJ];
__device__ float g_vb[BSZ * JJ];

// ---------------------------------------------------------------------------
// capsA: one CTA per (batch, i-quarter of 64 columns).
// ---------------------------------------------------------------------------
__global__ __launch_bounds__(256, 2)
void capsA(const float* __restrict__ x, const float* __restrict__ b_prev_in,
           int first, int write_b)
{
    extern __shared__ float sm[];
    float* xt  = sm;                    // [256][XS]
    float* usm = xt + 256 * XS;         // [32][US]
    float* ct  = usm + 32 * US;         // [32][CS]
    float* vbs = ct + 32 * CS;          // [32]

    const int b  = blockIdx.x >> 2;
    const int q  = blockIdx.x & 3;
    const int i0 = q * TI;
    const int t  = threadIdx.x;
    const float* xb = x + (size_t)b * (CC * II);
    const float* bp_base = b_prev_in ? b_prev_in : g_blog;

    if (!first) {
        const float4* ub4 = reinterpret_cast<const float4*>(g_u + (size_t)b * (JJ * CC));
#pragma unroll
        for (int it = 0; it < 8; it++) {
            int i4  = t + it * 256;          // 0..2047
            int row = i4 >> 6;
            int c4  = (i4 & 63) * 4;
            float4 v = ub4[i4];
            float* dst = &usm[row * US + c4];
            dst[0] = v.x; dst[1] = v.y; dst[2] = v.z; dst[3] = v.w;
        }
        if (t < JJ) vbs[t] = g_vb[b * JJ + t];
    }

    // stage x[:, i0:i0+64] -> xt[c][i-i0]
    {
        const int qq   = t & 3;
        const int row0 = t >> 2;
#pragma unroll
        for (int rep = 0; rep < 4; rep++) {
            const int c = row0 + rep * 64;
            const float4* src =
                reinterpret_cast<const float4*>(xb + (size_t)c * II + i0 + qq * 16);
            float* dst = &xt[c * XS + qq * 16];
#pragma unroll
            for (int k = 0; k < 4; k++) {
                float4 v4 = src[k];
                dst[k * 4 + 0] = v4.x; dst[k * 4 + 1] = v4.y;
                dst[k * 4 + 2] = v4.z; dst[k * 4 + 3] = v4.w;
            }
        }
    }
    __syncthreads();

    if (!first) {
        // delta GEMM: out [32 j][64 i] packed as i-pairs; split-K4 over c.
        const int h   = t >> 6;      // 0..3, c-quarter
        const int p   = t & 63;
        const int ipb = p & 7;       // ipair = ipb + 8*r
        const int jb  = p >> 3;      // j = jb*4 + n
        ull acc2[4][4];
#pragma unroll
        for (int n = 0; n < 4; n++)
#pragma unroll
            for (int r = 0; r < 4; r++) acc2[n][r] = 0ull;
        const int c0 = h * 64;
#pragma unroll 4
        for (int c = c0; c < c0 + 64; c++) {
            ull uv2[4], xv2[4];
#pragma unroll
            for (int n = 0; n < 4; n++) uv2[n] = fpack2(usm[(jb * 4 + n) * US + c]);
#pragma unroll
            for (int r = 0; r < 4; r++) xv2[r] = lds2(&xt[c * XS + 2 * (ipb + 8 * r)]);
#pragma unroll
            for (int n = 0; n < 4; n++)
#pragma unroll
                for (int r = 0; r < 4; r++)
                    acc2[n][r] = ffma2(uv2[n], xv2[r], acc2[n][r]);
        }
        // serialized split-K reduction into ct
        if (h == 0) {
#pragma unroll
            for (int n = 0; n < 4; n++)
#pragma unroll
                for (int r = 0; r < 4; r++)
                    sts2(&ct[(jb * 4 + n) * CS + 2 * (ipb + 8 * r)], acc2[n][r]);
        }
        __syncthreads();
#pragma unroll
        for (int hh = 1; hh < 4; hh++) {
            if (h == hh) {
#pragma unroll
                for (int n = 0; n < 4; n++)
#pragma unroll
                    for (int r = 0; r < 4; r++) {
                        float* pp = &ct[(jb * 4 + n) * CS + 2 * (ipb + 8 * r)];
                        sts2(pp, fadd2(lds2(pp), acc2[n][r]));
                    }
            }
            __syncthreads();
        }
    }

    // softmax over j per column i (64 columns, one thread each)
    if (t < TI) {
        const int i = i0 + t;
        const float* bp = bp_base + (size_t)b * (JJ * II) + i;
        float bv[32];
        float mx = -3.4e38f;
#pragma unroll
        for (int j = 0; j < 32; j++) {
            float val = bp[j * II];
            if (!first) val += ct[j * CS + t] + vbs[j];
            bv[j] = val;
            mx = fmaxf(mx, val);
        }
        if (write_b) {
            float* bo = g_blog + (size_t)b * (JJ * II) + i;
#pragma unroll
            for (int j = 0; j < 32; j++) bo[j * II] = bv[j];
        }
        float Z = 0.f;
#pragma unroll
        for (int j = 0; j < 32; j++) { float e = expf(bv[j] - mx); bv[j] = e; Z += e; }
        const float inv = 1.f / Z;
#pragma unroll
        for (int j = 0; j < 32; j++) ct[j * CS + t] = bv[j] * inv;
    }
    __syncthreads();

    // csum partial
    if (t < 32) {
        float s = 0.f;
#pragma unroll 8
        for (int i = 0; i < TI; i++) s += ct[t * CS + i];
        g_csum[(b * 4 + q) * JJ + t] = s;
    }

    // y GEMM partial: 8j x 4c per thread (warp: j-group g, c-half hc).
    // ct loads are warp-broadcast; xt traffic halved vs 4j x 8c.
    const int lane = t & 31;
    const int w    = t >> 5;
    const int g    = w & 3;      // j = g*8 + n
    const int hc   = w >> 2;     // c = hc*128 + lane + 32*m
    ull yacc2[8][4];
#pragma unroll
    for (int n = 0; n < 8; n++)
#pragma unroll
        for (int m = 0; m < 4; m++) yacc2[n][m] = 0ull;

#pragma unroll 2
    for (int ip = 0; ip < TI / 2; ip++) {
        ull cf2[8], xv2[4];
#pragma unroll
        for (int n = 0; n < 8; n++) cf2[n] = lds2(&ct[(g * 8 + n) * CS + 2 * ip]);
#pragma unroll
        for (int m = 0; m < 4; m++)
            xv2[m] = lds2(&xt[(hc * 128 + lane + 32 * m) * XS + 2 * ip]);
#pragma unroll
        for (int m = 0; m < 4; m++)
#pragma unroll
            for (int n = 0; n < 8; n++)
                yacc2[n][m] = ffma2(cf2[n], xv2[m], yacc2[n][m]);
    }

    float* yb = g_y + (size_t)(b * 4 + q) * (JJ * CC);
#pragma unroll
    for (int n = 0; n < 8; n++)
#pragma unroll
        for (int m = 0; m < 4; m++)
            yb[(g * 8 + n) * CC + hc * 128 + lane + 32 * m] = f2sum(yacc2[n][m]);
}

// ---------------------------------------------------------------------------
// capsB: one CTA per (j, batch-group of 32).
// ---------------------------------------------------------------------------
__global__ __launch_bounds__(256, 2)
void capsB(const float* __restrict__ W, const float* __restrict__ bias,
           float* __restrict__ out, int last)
{
    extern __shared__ float sm[];
    float* Wsm = sm;               // [64][WS]
    float* ysm = Wsm + 64 * WS;    // [32][YS]
    float* ssm = ysm + 32 * YS;    // [32][SS]
    float* bsm = ssm + 32 * SS;    // [64]
    float* fsm = bsm + 64;         // [32]
    float* csv = fsm + 32;         // [32]

    const int j  = blockIdx.x & 31;
    const int bg = blockIdx.x >> 5;
    const int t  = threadIdx.x;

    // stage W_j
    {
        const float4* Wj4 = reinterpret_cast<const float4*>(W + (size_t)j * (DD * CC));
#pragma unroll
        for (int it = 0; it < 16; it++) {
            int i4  = t + it * 256;
            int row = i4 >> 6;
            int c   = (i4 & 63) * 4;
            float4 v = Wj4[i4];
            float* dst = &Wsm[row * WS + c];
            dst[0] = v.x; dst[1] = v.y; dst[2] = v.z; dst[3] = v.w;
        }
    }
    if (t < DD) bsm[t] = bias[j * DD + t];
    if (t < 32) {
        float cs = 0.f;
#pragma unroll
        for (int q = 0; q < 4; q++)
            cs += g_csum[((bg * 32 + t) * 4 + q) * JJ + j];
        csv[t] = cs;
    }
    // stage y = sum of 4 quarter partials
    {
#pragma unroll
        for (int it = 0; it < 8; it++) {
            int i4 = t + it * 256;
            int bb = i4 >> 6;
            int c4 = i4 & 63;
            float4 a = make_float4(0.f, 0.f, 0.f, 0.f);
#pragma unroll
            for (int q = 0; q < 4; q++) {
                const float4* src = reinterpret_cast<const float4*>(
                    g_y + ((size_t)((bg * 32 + bb) * 4 + q) * JJ + j) * CC);
                float4 v = src[c4];
                a.x += v.x; a.y += v.y; a.z += v.z; a.w += v.w;
            }
            float* dst = &ysm[bb * YS + c4 * 4];
            dst[0] = a.x; dst[1] = a.y; dst[2] = a.z; dst[3] = a.w;
        }
    }
    __syncthreads();

    // GEMM1: S[32 b][64 d], K-packed over c, split-K2; csum*bias folded into
    // the h==1 writeback.
    {
        const int h   = t >> 7;
        const int p   = t & 127;
        const int db  = p & 15;
        const int bgr = p >> 4;
        ull acc2[4][4];
#pragma unroll
        for (int n = 0; n < 4; n++)
#pragma unroll
            for (int r = 0; r < 4; r++) acc2[n][r] = 0ull;
        const int cp0 = h * 64;
#pragma unroll 4
        for (int cp = cp0; cp < cp0 + 64; cp++) {
            ull yv2[4], wv2[4];
#pragma unroll
            for (int n = 0; n < 4; n++) yv2[n] = lds2(&ysm[(bgr * 4 + n) * YS + 2 * cp]);
#pragma unroll
            for (int r = 0; r < 4; r++) wv2[r] = lds2(&Wsm[(db + 16 * r) * WS + 2 * cp]);
#pragma unroll
            for (int n = 0; n < 4; n++)
#pragma unroll
                for (int r = 0; r < 4; r++)
                    acc2[n][r] = ffma2(yv2[n], wv2[r], acc2[n][r]);
        }
        if (h == 0) {
#pragma unroll
            for (int n = 0; n < 4; n++)
#pragma unroll
                for (int r = 0; r < 4; r++)
                    ssm[(bgr * 4 + n) * SS + db + 16 * r] = f2sum(acc2[n][r]);
        }
        __syncthreads();
        if (h == 1) {
#pragma unroll
            for (int n = 0; n < 4; n++) {
                const int bb = bgr * 4 + n;
                const float cv = csv[bb];
#pragma unroll
                for (int r = 0; r < 4; r++) {
                    const int d = db + 16 * r;
                    ssm[bb * SS + d] += f2sum(acc2[n][r]) + cv * bsm[d];
                }
            }
        }
        __syncthreads();
    }

    // squash factor per batch: 8 lanes per b, butterfly reduce
    {
        const int bb = t >> 3, dg = t & 7;
        float p2 = 0.f;
#pragma unroll
        for (int k = 0; k < 8; k++) {
            float s = ssm[bb * SS + dg + 8 * k];
            p2 = fmaf(s, s, p2);
        }
        p2 += __shfl_xor_sync(0xffffffffu, p2, 4);
        p2 += __shfl_xor_sync(0xffffffffu, p2, 2);
        p2 += __shfl_xor_sync(0xffffffffu, p2, 1);
        if (dg == 0) {
            const float nn = sqrtf(p2);
            fsm[bb] = nn / (1.f + p2);
        }
    }
    __syncthreads();

    // v = s*factor in place; write output if last
#pragma unroll
    for (int k = 0; k < 8; k++) {
        int idx = t + k * 256;
        int bb = idx >> 6, d = idx & 63;
        float v = ssm[bb * SS + d] * fsm[bb];
        ssm[bb * SS + d] = v;
        if (last) out[((size_t)(bg * 32 + bb) * JJ + j) * DD + d] = v;
    }
    __syncthreads();

    if (!last) {
        // vb[b] = v . bias  (8 lanes per b, butterfly reduce)
        {
            const int bb = t >> 3, dg = t & 7;
            float p3 = 0.f;
#pragma unroll
            for (int k = 0; k < 8; k++)
                p3 = fmaf(ssm[bb * SS + dg + 8 * k], bsm[dg + 8 * k], p3);
            p3 += __shfl_xor_sync(0xffffffffu, p3, 4);
            p3 += __shfl_xor_sync(0xffffffffu, p3, 2);
            p3 += __shfl_xor_sync(0xffffffffu, p3, 1);
            if (dg == 0) g_vb[(bg * 32 + bb) * JJ + j] = p3;
        }
        // GEMM2: U[32 b][256 c] output-packed along c, K = 64
        const int ci = t & 31;   // cpair = ci + 32*m
        const int bi = t >> 5;   // b = bi + 8*n
        ull ua2[4][4];
#pragma unroll
        for (int n = 0; n < 4; n++)
#pragma unroll
            for (int m = 0; m < 4; m++) ua2[n][m] = 0ull;
#pragma unroll 4
        for (int d = 0; d < 64; d++) {
            ull vv2[4], wv2[4];
#pragma unroll
            for (int n = 0; n < 4; n++) vv2[n] = fpack2(ssm[(bi + 8 * n) * SS + d]);
#pragma unroll
            for (int m = 0; m < 4; m++) wv2[m] = lds2(&Wsm[d * WS + 2 * (ci + 32 * m)]);
#pragma unroll
            for (int n = 0; n < 4; n++)
#pragma unroll
                for (int m = 0; m < 4; m++)
                    ua2[n][m] = ffma2(vv2[n], wv2[m], ua2[n][m]);
        }
#pragma unroll
        for (int n = 0; n < 4; n++)
#pragma unroll
            for (int m = 0; m < 4; m++)
                *reinterpret_cast<ull*>(
                    &g_u[((size_t)(bg * 32 + bi + 8 * n) * JJ + j) * CC
                         + 2 * (ci + 32 * m)]) = ua2[n][m];
    }
}

extern "C" void kernel_launch(void* const* d_in, const int* in_sizes, int n_in,
                              void* d_out, int out_size)
{
    const float* x     = (const float*)d_in[0];
    const float* W     = (const float*)d_in[1];
    const float* bias  = (const float*)d_in[2];
    const float* binit = (const float*)d_in[3];
    float* out = (float*)d_out;

    const int SMEM_A = (256 * XS + 32 * US + 32 * CS + 32) * (int)sizeof(float);
    const int SMEM_B = (64 * WS + 32 * YS + 32 * SS + 64 + 32 + 32) * (int)sizeof(float);

    cudaFuncSetAttribute(capsA, cudaFuncAttributeMaxDynamicSharedMemorySize, SMEM_A);
    cudaFuncSetAttribute(capsB, cudaFuncAttributeMaxDynamicSharedMemorySize, SMEM_B);

    capsA<<<BSZ * NQ, 256, SMEM_A>>>(x, binit, /*first=*/1, /*write_b=*/0);
    capsB<<<256, 256, SMEM_B>>>(W, bias, nullptr, /*last=*/0);
    capsA<<<BSZ * NQ, 256, SMEM_A>>>(x, binit, 0, 1);
    capsB<<<256, 256, SMEM_B>>>(W, bias, nullptr, 0);
    capsA<<<BSZ * NQ, 256, SMEM_A>>>(x, nullptr, 0, 0);
    capsB<<<256, 256, SMEM_B>>>(W, bias, out, 1);
}